// round 8
// baseline (speedup 1.0000x reference)
#include <cuda_runtime.h>

#define HID 1024
#define NSAMP 1024
#define TSTEPS 98
#define G 8            // samples per CTA
#define NTHR 256       // threads per CTA; thread owns units 4*tid .. 4*tid+3
#define NCTA (NSAMP / G)

__device__ float g_W2T[HID * HID];
__device__ float g_W3T[HID * HID];
__device__ float g_fr[3];

// ---------------------------------------------------------------------------
__global__ void prep_kernel(const float* __restrict__ W2,
                            const float* __restrict__ W3) {
    __shared__ float tile[32][33];
    const float* src = (blockIdx.z == 0) ? W2 : W3;
    float* dst = (blockIdx.z == 0) ? g_W2T : g_W3T;
    int bx = blockIdx.x * 32, by = blockIdx.y * 32;
    tile[threadIdx.y][threadIdx.x] = src[(by + threadIdx.y) * HID + bx + threadIdx.x];
    __syncthreads();
    dst[(bx + threadIdx.y) * HID + by + threadIdx.x] = tile[threadIdx.x][threadIdx.y];
    if (blockIdx.x == 0 && blockIdx.y == 0 && blockIdx.z == 0 &&
        threadIdx.y == 0 && threadIdx.x < 3)
        g_fr[threadIdx.x] = 0.0f;
}

// ---------------------------------------------------------------------------
static __device__ __forceinline__ unsigned long long addf32x2(
    unsigned long long a, unsigned long long b) {
    unsigned long long o;
    asm("add.rn.f32x2 %0, %1, %2;" : "=l"(o) : "l"(a), "l"(b));
    return o;
}

static __device__ __forceinline__ unsigned spread4(unsigned m) {
    return ((m & 0xFu) * 0x00204081u) & 0x01010101u;
}

static __device__ __forceinline__ unsigned bytesum(unsigned v, unsigned c) {
    unsigned ones = 0x01010101u;
    unsigned r;
    asm("dp4a.u32.u32 %0, %1, %2, %3;" : "=r"(r) : "r"(v), "r"(ones), "r"(c));
    return r;
}

// exclusive scan over 256 threads (8 warps); returns total to all threads
static __device__ __forceinline__ void block_scan(int v, int tid, int* s_warp,
                                                  int& excl, int& total) {
    int lane = tid & 31, wid = tid >> 5;
    int x = v;
#pragma unroll
    for (int o = 1; o < 32; o <<= 1) {
        int y = __shfl_up_sync(0xffffffffu, x, o);
        if (lane >= o) x += y;
    }
    __syncthreads();
    if (lane == 31) s_warp[wid] = x;
    __syncthreads();
    int pre = 0, tot = 0;
#pragma unroll
    for (int w = 0; w < 8; w++) {
        int sw = s_warp[w];
        pre += (w < wid) ? sw : 0;
        tot += sw;
    }
    excl = pre + x - v;
    total = tot;
}

union F2U { unsigned long long u; float2 f; };
union F4U { float4 f; unsigned long long u[2]; };

// membrane update for a unit pair (packed drive), per-unit eligibility
static __device__ __forceinline__ void upd_pair(float* mX, float* mY,
                                                const unsigned long long* d,
                                                bool elX, bool elY,
                                                unsigned& pX, unsigned& pY) {
    unsigned a = 0, b = 0;
#pragma unroll
    for (int g = 0; g < G; g++) {
        F2U u;
        u.u = d[g];
        if (elX) {
            float base = ((pX >> g) & 1) ? 0.0f : mX[g] * 0.5f;
            float nm = base + u.f.x;
            mX[g] = nm;
            if (nm > 0.5f) a |= (1u << g);
        }
        if (elY) {
            float base = ((pY >> g) & 1) ? 0.0f : mY[g] * 0.5f;
            float nm = base + u.f.y;
            mY[g] = nm;
            if (nm > 0.5f) b |= (1u << g);
        }
    }
    if (elX) pX = a; else pX = 0;
    if (elY) pY = b; else pY = 0;
}

// 8 samples x (1 pred test + 2 packed adds) for one 4-unit row slice
#define ACCQ(e, w)                                                          \
    do {                                                                    \
        unsigned _m = (e) >> 10;                                            \
        if (_m & 1u)   { accL[0] = addf32x2(accL[0], (w).u[0]);             \
                         accH[0] = addf32x2(accH[0], (w).u[1]); }           \
        if (_m & 2u)   { accL[1] = addf32x2(accL[1], (w).u[0]);             \
                         accH[1] = addf32x2(accH[1], (w).u[1]); }           \
        if (_m & 4u)   { accL[2] = addf32x2(accL[2], (w).u[0]);             \
                         accH[2] = addf32x2(accH[2], (w).u[1]); }           \
        if (_m & 8u)   { accL[3] = addf32x2(accL[3], (w).u[0]);             \
                         accH[3] = addf32x2(accH[3], (w).u[1]); }           \
        if (_m & 16u)  { accL[4] = addf32x2(accL[4], (w).u[0]);             \
                         accH[4] = addf32x2(accH[4], (w).u[1]); }           \
        if (_m & 32u)  { accL[5] = addf32x2(accL[5], (w).u[0]);             \
                         accH[5] = addf32x2(accH[5], (w).u[1]); }           \
        if (_m & 64u)  { accL[6] = addf32x2(accL[6], (w).u[0]);             \
                         accH[6] = addf32x2(accH[6], (w).u[1]); }           \
        if (_m & 128u) { accL[7] = addf32x2(accL[7], (w).u[0]);             \
                         accH[7] = addf32x2(accH[7], (w).u[1]); }           \
    } while (0)

// union-row gather, 4 rows in flight; base = (float4*)WT + tid, row at h<<8
static __device__ __forceinline__ void gather(const unsigned* __restrict__ list,
                                              int cnt,
                                              const float4* __restrict__ base,
                                              unsigned long long accL[G],
                                              unsigned long long accH[G]) {
    const int nb = cnt >> 2;
    if (nb > 0) {
        uint4 c = *reinterpret_cast<const uint4*>(list);
        unsigned e0 = c.x, e1 = c.y, e2 = c.z, e3 = c.w;
        F4U w0, w1, w2, w3;
        w0.f = __ldg(base + ((e0 & 1023u) << 8));
        w1.f = __ldg(base + ((e1 & 1023u) << 8));
        w2.f = __ldg(base + ((e2 & 1023u) << 8));
        w3.f = __ldg(base + ((e3 & 1023u) << 8));
        for (int b = 0; b < nb; b++) {
            unsigned f0 = e0, f1 = e1, f2 = e2, f3 = e3;
            F4U v0 = w0, v1 = w1, v2 = w2, v3 = w3;
            if (b + 1 < nb) {
                uint4 n = *reinterpret_cast<const uint4*>(list + 4 * (b + 1));
                e0 = n.x; e1 = n.y; e2 = n.z; e3 = n.w;
                w0.f = __ldg(base + ((e0 & 1023u) << 8));
                w1.f = __ldg(base + ((e1 & 1023u) << 8));
                w2.f = __ldg(base + ((e2 & 1023u) << 8));
                w3.f = __ldg(base + ((e3 & 1023u) << 8));
            }
            ACCQ(f0, v0);
            ACCQ(f1, v1);
            ACCQ(f2, v2);
            ACCQ(f3, v3);
        }
    }
    for (int i = nb << 2; i < cnt; i++) {
        unsigned e = list[i];
        F4U wv;
        wv.f = __ldg(base + ((e & 1023u) << 8));
        ACCQ(e, wv);
    }
}

// ---------------------------------------------------------------------------
__global__ void __launch_bounds__(NTHR) snn_kernel(
    const float* __restrict__ input,
    const float* __restrict__ W1, const float* __restrict__ b1,
    const float* __restrict__ b2, const float* __restrict__ b3,
    const float* __restrict__ W4, const float* __restrict__ b4,
    float* __restrict__ out) {
    __shared__ __align__(16) unsigned listA[HID];
    __shared__ __align__(16) unsigned listB[HID];
    __shared__ int s_warp[8];
    __shared__ float xsh[G * 8];
    __shared__ float4 s_red4[8];
    __shared__ __align__(16) ulonglong2 dcsh[G * NTHR];  // 32KB const L1 drive

    const int tid = threadIdx.x;
    const int n0 = blockIdx.x * G;
    const int h0 = 4 * tid;

    // per-unit phase counters: u_k = (t - (h0+k)) mod 98, and u mod 3
    int u[4], r3[4];
#pragma unroll
    for (int k = 0; k < 4; k++) {
        u[k] = (98 - ((h0 + k) % 98)) % 98;
        r3[k] = u[k] % 3;
    }

    float m1[4][G], m2[4][G], m3[4][G];
#pragma unroll
    for (int k = 0; k < 4; k++)
#pragma unroll
        for (int g = 0; g < G; g++) {
            m1[k][g] = 0; m2[k][g] = 0; m3[k][g] = 0;
        }
    unsigned p1[4] = {0,0,0,0}, p2[4] = {0,0,0,0}, p3[4] = {0,0,0,0};
    unsigned ss1l[4] = {0,0,0,0}, ss1h[4] = {0,0,0,0};
    unsigned ss2l[4] = {0,0,0,0}, ss2h[4] = {0,0,0,0};
    unsigned ss3l[4] = {0,0,0,0}, ss3h[4] = {0,0,0,0};

    F4U bq2, bq3;
    bq2.f = __ldg(reinterpret_cast<const float4*>(b2) + tid);
    bq3.f = __ldg(reinterpret_cast<const float4*>(b3) + tid);

    const float4* W14 = reinterpret_cast<const float4*>(W1);
    const float4* base2 = reinterpret_cast<const float4*>(g_W2T) + tid;
    const float4* base3 = reinterpret_cast<const float4*>(g_W3T) + tid;

    // constant layer-1 drive (t >= 12 uses input slice at 776): to SMEM
    if (tid < G * 8)
        xsh[tid] = __ldg(input + (n0 + (tid >> 3)) * 784 + 776 + (tid & 7));
    __syncthreads();
    {
        float4 bq1 = __ldg(reinterpret_cast<const float4*>(b1) + tid);
        float w1r[4][8];
#pragma unroll
        for (int k = 0; k < 4; k++) {
            float4 a = __ldg(W14 + (h0 + k) * 2);
            float4 c = __ldg(W14 + (h0 + k) * 2 + 1);
            w1r[k][0] = a.x; w1r[k][1] = a.y; w1r[k][2] = a.z; w1r[k][3] = a.w;
            w1r[k][4] = c.x; w1r[k][5] = c.y; w1r[k][6] = c.z; w1r[k][7] = c.w;
        }
        float bb[4] = {bq1.x, bq1.y, bq1.z, bq1.w};
#pragma unroll
        for (int g = 0; g < G; g++) {
            const float* x = &xsh[g * 8];
            float s[4];
#pragma unroll
            for (int k = 0; k < 4; k++) {
                float acc = bb[k];
#pragma unroll
                for (int i = 0; i < 8; i++) acc += x[i] * w1r[k][i];
                s[k] = acc;
            }
            F4U pk;
            pk.f = make_float4(s[0], s[1], s[2], s[3]);
            dcsh[g * NTHR + tid] = make_ulonglong2(pk.u[0], pk.u[1]);
        }
    }
    __syncthreads();

    for (int t = 0; t < TSTEPS; t++) {
        // ---------- layer 1 drive (packed pairs: L = units 0,1; H = 2,3) ---
        unsigned long long d1L[G], d1H[G];
        if (t < 12) {
            if (tid < G * 8)
                xsh[tid] =
                    __ldg(input + (n0 + (tid >> 3)) * 784 + t * 8 + (tid & 7));
            __syncthreads();
            float4 bq1 = __ldg(reinterpret_cast<const float4*>(b1) + tid);
            float w1r[4][8];
#pragma unroll
            for (int k = 0; k < 4; k++) {
                float4 a = __ldg(W14 + (h0 + k) * 2);
                float4 c = __ldg(W14 + (h0 + k) * 2 + 1);
                w1r[k][0] = a.x; w1r[k][1] = a.y; w1r[k][2] = a.z; w1r[k][3] = a.w;
                w1r[k][4] = c.x; w1r[k][5] = c.y; w1r[k][6] = c.z; w1r[k][7] = c.w;
            }
            float bb[4] = {bq1.x, bq1.y, bq1.z, bq1.w};
#pragma unroll
            for (int g = 0; g < G; g++) {
                const float* x = &xsh[g * 8];
                float s[4];
#pragma unroll
                for (int k = 0; k < 4; k++) {
                    float acc = bb[k];
#pragma unroll
                    for (int i = 0; i < 8; i++) acc += x[i] * w1r[k][i];
                    s[k] = acc;
                }
                F4U pk;
                pk.f = make_float4(s[0], s[1], s[2], s[3]);
                d1L[g] = pk.u[0];
                d1H[g] = pk.u[1];
            }
            __syncthreads();
        } else {
#pragma unroll
            for (int g = 0; g < G; g++) {
                ulonglong2 v = dcsh[g * NTHR + tid];
                d1L[g] = v.x;
                d1H[g] = v.y;
            }
        }

        // ---------- layer 1 update (cycle 2) ----------
        upd_pair(m1[0], m1[1], d1L, (u[0] & 1) == 0, (u[1] & 1) == 0, p1[0], p1[1]);
        upd_pair(m1[2], m1[3], d1H, (u[2] & 1) == 0, (u[3] & 1) == 0, p1[2], p1[3]);
#pragma unroll
        for (int k = 0; k < 4; k++) {
            ss1l[k] += spread4(p1[k]);
            ss1h[k] += spread4(p1[k] >> 4);
        }

        int excl, cnt;
        {
            int cl = (p1[0] ? 1 : 0) + (p1[1] ? 1 : 0) + (p1[2] ? 1 : 0) +
                     (p1[3] ? 1 : 0);
            block_scan(cl, tid, s_warp, excl, cnt);
            int p = excl;
#pragma unroll
            for (int k = 0; k < 4; k++)
                if (p1[k]) listA[p++] = (p1[k] << 10) | (unsigned)(h0 + k);
        }
        __syncthreads();

        // ---------- layer 2: gather + update (cycle 3) ----------
        unsigned long long accL[G], accH[G];
#pragma unroll
        for (int g = 0; g < G; g++) { accL[g] = bq2.u[0]; accH[g] = bq2.u[1]; }
        gather(listA, cnt, base2, accL, accH);

        upd_pair(m2[0], m2[1], accL, r3[0] == 0, r3[1] == 0, p2[0], p2[1]);
        upd_pair(m2[2], m2[3], accH, r3[2] == 0, r3[3] == 0, p2[2], p2[3]);
#pragma unroll
        for (int k = 0; k < 4; k++) {
            ss2l[k] += spread4(p2[k]);
            ss2h[k] += spread4(p2[k] >> 4);
        }

        {
            int cl = (p2[0] ? 1 : 0) + (p2[1] ? 1 : 0) + (p2[2] ? 1 : 0) +
                     (p2[3] ? 1 : 0);
            block_scan(cl, tid, s_warp, excl, cnt);
            int p = excl;
#pragma unroll
            for (int k = 0; k < 4; k++)
                if (p2[k]) listB[p++] = (p2[k] << 10) | (unsigned)(h0 + k);
        }
        __syncthreads();

        // ---------- layer 3: gather + update (cycle 4) ----------
#pragma unroll
        for (int g = 0; g < G; g++) { accL[g] = bq3.u[0]; accH[g] = bq3.u[1]; }
        gather(listB, cnt, base3, accL, accH);

        upd_pair(m3[0], m3[1], accL, (u[0] & 3) == 0, (u[1] & 3) == 0, p3[0], p3[1]);
        upd_pair(m3[2], m3[3], accH, (u[2] & 3) == 0, (u[3] & 3) == 0, p3[2], p3[3]);
#pragma unroll
        for (int k = 0; k < 4; k++) {
            ss3l[k] += spread4(p3[k]);
            ss3h[k] += spread4(p3[k] >> 4);
        }

#pragma unroll
        for (int k = 0; k < 4; k++) {
            if (++u[k] == 98) { u[k] = 0; r3[k] = 0; }
            else if (++r3[k] == 3) r3[k] = 0;
        }
    }

    // ------------------------- epilogue -------------------------
    const float inv = 1.0f / 98.0f;

    // hidden_spk = ss / 98; float4 per (layer, sample)
#pragma unroll
    for (int g = 0; g < G; g++) {
        int sh = 8 * (g & 3);
        const unsigned* l1 = (g < 4) ? ss1l : ss1h;
        const unsigned* l2 = (g < 4) ? ss2l : ss2h;
        const unsigned* l3 = (g < 4) ? ss3l : ss3h;
        float4 v1 = make_float4((float)((l1[0] >> sh) & 255u) * inv,
                                (float)((l1[1] >> sh) & 255u) * inv,
                                (float)((l1[2] >> sh) & 255u) * inv,
                                (float)((l1[3] >> sh) & 255u) * inv);
        float4 v2 = make_float4((float)((l2[0] >> sh) & 255u) * inv,
                                (float)((l2[1] >> sh) & 255u) * inv,
                                (float)((l2[2] >> sh) & 255u) * inv,
                                (float)((l2[3] >> sh) & 255u) * inv);
        float4 v3 = make_float4((float)((l3[0] >> sh) & 255u) * inv,
                                (float)((l3[1] >> sh) & 255u) * inv,
                                (float)((l3[2] >> sh) & 255u) * inv,
                                (float)((l3[3] >> sh) & 255u) * inv);
        *reinterpret_cast<float4*>(out + 10240 + 0 * 1048576 + (n0 + g) * HID + h0) = v1;
        *reinterpret_cast<float4*>(out + 10240 + 1 * 1048576 + (n0 + g) * HID + h0) = v2;
        *reinterpret_cast<float4*>(out + 10240 + 2 * 1048576 + (n0 + g) * HID + h0) = v3;
    }

    // spike counts as floats for output GEMM
    float s3[4][G];
#pragma unroll
    for (int k = 0; k < 4; k++)
#pragma unroll
        for (int g = 0; g < G; g++)
            s3[k][g] = (float)(((g < 4 ? ss3l[k] : ss3h[k]) >> (8 * (g & 3))) & 255u);

    const int lane = tid & 31, wid = tid >> 5;

    // outputs[n] = (ss3 @ W4^T)/98 + b4
    for (int o = 0; o < 10; o++) {
        float4 w4 = __ldg(reinterpret_cast<const float4*>(W4 + o * HID) + tid);
#pragma unroll
        for (int half = 0; half < 2; half++) {
            float4 v;
            v.x = s3[0][half * 4 + 0] * w4.x + s3[1][half * 4 + 0] * w4.y +
                  s3[2][half * 4 + 0] * w4.z + s3[3][half * 4 + 0] * w4.w;
            v.y = s3[0][half * 4 + 1] * w4.x + s3[1][half * 4 + 1] * w4.y +
                  s3[2][half * 4 + 1] * w4.z + s3[3][half * 4 + 1] * w4.w;
            v.z = s3[0][half * 4 + 2] * w4.x + s3[1][half * 4 + 2] * w4.y +
                  s3[2][half * 4 + 2] * w4.z + s3[3][half * 4 + 2] * w4.w;
            v.w = s3[0][half * 4 + 3] * w4.x + s3[1][half * 4 + 3] * w4.y +
                  s3[2][half * 4 + 3] * w4.z + s3[3][half * 4 + 3] * w4.w;
#pragma unroll
            for (int off = 16; off > 0; off >>= 1) {
                v.x += __shfl_down_sync(0xffffffffu, v.x, off);
                v.y += __shfl_down_sync(0xffffffffu, v.y, off);
                v.z += __shfl_down_sync(0xffffffffu, v.z, off);
                v.w += __shfl_down_sync(0xffffffffu, v.w, off);
            }
            if (lane == 0) s_red4[wid] = v;
            __syncthreads();
            if (tid == 0) {
                float4 s = make_float4(0, 0, 0, 0);
#pragma unroll
                for (int w = 0; w < 8; w++) {
                    s.x += s_red4[w].x; s.y += s_red4[w].y;
                    s.z += s_red4[w].z; s.w += s_red4[w].w;
                }
                float bo = __ldg(b4 + o);
                out[(n0 + half * 4 + 0) * 10 + o] = s.x / 98.0f + bo;
                out[(n0 + half * 4 + 1) * 10 + o] = s.y / 98.0f + bo;
                out[(n0 + half * 4 + 2) * 10 + o] = s.z / 98.0f + bo;
                out[(n0 + half * 4 + 3) * 10 + o] = s.w / 98.0f + bo;
            }
            __syncthreads();
        }
    }

    // layer firing-rate partial sums (exact integers in fp32)
    unsigned c1 = 0, c2 = 0, c3 = 0;
#pragma unroll
    for (int k = 0; k < 4; k++) {
        c1 = bytesum(ss1l[k], c1); c1 = bytesum(ss1h[k], c1);
        c2 = bytesum(ss2l[k], c2); c2 = bytesum(ss2h[k], c2);
        c3 = bytesum(ss3l[k], c3); c3 = bytesum(ss3h[k], c3);
    }
    {
        float4 v = make_float4((float)c1, (float)c2, (float)c3, 0.0f);
#pragma unroll
        for (int off = 16; off > 0; off >>= 1) {
            v.x += __shfl_down_sync(0xffffffffu, v.x, off);
            v.y += __shfl_down_sync(0xffffffffu, v.y, off);
            v.z += __shfl_down_sync(0xffffffffu, v.z, off);
        }
        if (lane == 0) s_red4[wid] = v;
        __syncthreads();
        if (tid == 0) {
            float s0 = 0, s1 = 0, s2 = 0;
#pragma unroll
            for (int w = 0; w < 8; w++) {
                s0 += s_red4[w].x; s1 += s_red4[w].y; s2 += s_red4[w].z;
            }
            atomicAdd(&g_fr[0], s0);
            atomicAdd(&g_fr[1], s1);
            atomicAdd(&g_fr[2], s2);
        }
    }
}

__global__ void finalize_kernel(float* __restrict__ out) {
    if (threadIdx.x < 3)
        out[3155968 + threadIdx.x] = g_fr[threadIdx.x] / 102760448.0f;
}

extern "C" void kernel_launch(void* const* d_in, const int* in_sizes, int n_in,
                              void* d_out, int out_size) {
    const float* input = (const float*)d_in[0];
    const float* W1 = (const float*)d_in[1];
    const float* b1 = (const float*)d_in[2];
    const float* W2 = (const float*)d_in[3];
    const float* b2 = (const float*)d_in[4];
    const float* W3 = (const float*)d_in[5];
    const float* b3 = (const float*)d_in[6];
    const float* W4 = (const float*)d_in[7];
    const float* b4 = (const float*)d_in[8];
    (void)in_sizes; (void)n_in; (void)out_size;

    dim3 pgrid(HID / 32, HID / 32, 2);
    prep_kernel<<<pgrid, dim3(32, 32)>>>(W2, W3);
    snn_kernel<<<NCTA, NTHR>>>(input, W1, b1, b2, b3, W4, b4, (float*)d_out);
    finalize_kernel<<<1, 32>>>((float*)d_out);
}

// round 9
// speedup vs baseline: 1.1714x; 1.1714x over previous
#include <cuda_runtime.h>

#define HID 1024
#define NSAMP 1024
#define TSTEPS 98
#define G 8            // samples per CTA
#define NTHR 256       // threads per CTA; thread owns 4 column-slots (c=tid+256s)
#define NCTA (NSAMP / G)

__device__ float g_W2J[HID * HID];  // [src h][reordered dest col]
__device__ float g_W3J[HID * HID];
__device__ int g_u2[HID];           // col -> dest unit (layer 2 ordering)
__device__ int g_u3[HID];           // col -> dest unit (layer 3 ordering)
__device__ int g_S2[99];            // group prefix sums (98 groups)
__device__ int g_S3[2][50];         // per-parity group prefix sums (49 groups)
__device__ float g_fr[3];

// ---------------------------------------------------------------------------
__global__ void init_tables() {
    if (threadIdx.x != 0 || blockIdx.x != 0) return;
    // Layer 2 (cycle 3): group gamma in [0,98): rho = 3*gamma mod 98.
    // Eligible at t  <=>  gamma in [33t-32, 33t] mod 98  (33 groups).
    int s = 0;
    for (int g = 0; g < 98; g++) {
        g_S2[g] = s;
        int rho = (3 * g) % 98;
        int cnt = (rho < 44) ? 11 : 10;
        for (int i = 0; i < cnt; i++) g_u2[s + i] = rho + 98 * i;
        s += cnt;
    }
    g_S2[98] = s;  // 1024
    // Layer 3 (cycle 4): parity p block; group g3 in [0,49): q = 2*g3 mod 49,
    // rho = 2q+p. Eligible at t=2*tau+p <=> g3 in [25*tau-24, 25*tau] mod 49.
    for (int p = 0; p < 2; p++) {
        int sp = 512 * p;
        for (int g3 = 0; g3 < 49; g3++) {
            g_S3[p][g3] = sp;
            int q = (2 * g3) % 49;
            int rho = 2 * q + p;
            int cnt = (rho < 44) ? 11 : 10;
            for (int i = 0; i < cnt; i++) g_u3[sp + i] = rho + 98 * i;
            sp += cnt;
        }
        g_S3[p][49] = sp;  // 512*(p+1)
    }
    g_fr[0] = 0.0f; g_fr[1] = 0.0f; g_fr[2] = 0.0f;
}

// ---------------------------------------------------------------------------
// Build reordered transposes: gWJ[h][c] = W[u(c)][h]
__global__ void prep_kernel(const float* __restrict__ W2,
                            const float* __restrict__ W3) {
    __shared__ float tile[32][33];
    __shared__ int uu[32];
    const float* src = (blockIdx.z == 0) ? W2 : W3;
    float* dst = (blockIdx.z == 0) ? g_W2J : g_W3J;
    const int* umap = (blockIdx.z == 0) ? g_u2 : g_u3;
    int c0 = blockIdx.x * 32, h0 = blockIdx.y * 32;
    int tx = threadIdx.x, ty = threadIdx.y;
    if (ty == 0) uu[tx] = umap[c0 + tx];
    __syncthreads();
    tile[ty][tx] = src[uu[ty] * HID + h0 + tx];  // coalesced read over h
    __syncthreads();
    dst[(h0 + ty) * HID + c0 + tx] = tile[tx][ty];  // coalesced write over c
}

// ---------------------------------------------------------------------------
static __device__ __forceinline__ unsigned long long addf32x2(
    unsigned long long a, unsigned long long b) {
    unsigned long long o;
    asm("add.rn.f32x2 %0, %1, %2;" : "=l"(o) : "l"(a), "l"(b));
    return o;
}

static __device__ __forceinline__ unsigned spread4(unsigned m) {
    return ((m & 0xFu) * 0x00204081u) & 0x01010101u;
}

static __device__ __forceinline__ unsigned bytesum(unsigned v, unsigned c) {
    unsigned ones = 0x01010101u;
    unsigned r;
    asm("dp4a.u32.u32 %0, %1, %2, %3;" : "=r"(r) : "r"(v), "r"(ones), "r"(c));
    return r;
}

// exclusive scan over 256 threads (8 warps); returns total to all threads
static __device__ __forceinline__ void block_scan(int v, int tid, int* s_warp,
                                                  int& excl, int& total) {
    int lane = tid & 31, wid = tid >> 5;
    int x = v;
#pragma unroll
    for (int o = 1; o < 32; o <<= 1) {
        int y = __shfl_up_sync(0xffffffffu, x, o);
        if (lane >= o) x += y;
    }
    __syncthreads();
    if (lane == 31) s_warp[wid] = x;
    __syncthreads();
    int pre = 0, tot = 0;
#pragma unroll
    for (int w = 0; w < 8; w++) {
        int sw = s_warp[w];
        pre += (w < wid) ? sw : 0;
        tot += sw;
    }
    excl = pre + x - v;
    total = tot;
}

union F2U { unsigned long long u; float2 f; };

// 8 predicated packed adds for one row (mask in bits [10:18) of e)
#define ACC8P(e, wv)                                         \
    do {                                                     \
        unsigned _m = (e) >> 10;                             \
        if (_m & 1u)   acc[0] = addf32x2(acc[0], (wv));      \
        if (_m & 2u)   acc[1] = addf32x2(acc[1], (wv));      \
        if (_m & 4u)   acc[2] = addf32x2(acc[2], (wv));      \
        if (_m & 8u)   acc[3] = addf32x2(acc[3], (wv));      \
        if (_m & 16u)  acc[4] = addf32x2(acc[4], (wv));      \
        if (_m & 32u)  acc[5] = addf32x2(acc[5], (wv));      \
        if (_m & 64u)  acc[6] = addf32x2(acc[6], (wv));      \
        if (_m & 128u) acc[7] = addf32x2(acc[7], (wv));      \
    } while (0)

// Union-row gather over 1-2 in-window columns per thread, 4 rows in flight.
static __device__ __forceinline__ void gatherW(
    const unsigned* __restrict__ list, int cnt,
    const float* __restrict__ W, int cA, int cB,
    bool hasA, bool hasB, unsigned long long acc[G]) {
    const float* __restrict__ pA = W + cA;
    const float* __restrict__ pB = W + cB;
    const int nb = cnt >> 2;
    if (nb > 0) {
        uint4 c = *reinterpret_cast<const uint4*>(list);
        unsigned e0 = c.x, e1 = c.y, e2 = c.z, e3 = c.w;
        float a0 = 0.f, a1 = 0.f, a2 = 0.f, a3 = 0.f;
        float b0 = 0.f, b1 = 0.f, b2 = 0.f, b3 = 0.f;
        if (hasA) {
            a0 = __ldg(pA + ((e0 & 1023u) << 10));
            a1 = __ldg(pA + ((e1 & 1023u) << 10));
            a2 = __ldg(pA + ((e2 & 1023u) << 10));
            a3 = __ldg(pA + ((e3 & 1023u) << 10));
        }
        if (hasB) {
            b0 = __ldg(pB + ((e0 & 1023u) << 10));
            b1 = __ldg(pB + ((e1 & 1023u) << 10));
            b2 = __ldg(pB + ((e2 & 1023u) << 10));
            b3 = __ldg(pB + ((e3 & 1023u) << 10));
        }
        for (int b = 0; b < nb; b++) {
            unsigned f0 = e0, f1 = e1, f2 = e2, f3 = e3;
            float x0 = a0, x1 = a1, x2 = a2, x3 = a3;
            float y0 = b0, y1 = b1, y2 = b2, y3 = b3;
            if (b + 1 < nb) {
                uint4 n = *reinterpret_cast<const uint4*>(list + 4 * (b + 1));
                e0 = n.x; e1 = n.y; e2 = n.z; e3 = n.w;
                if (hasA) {
                    a0 = __ldg(pA + ((e0 & 1023u) << 10));
                    a1 = __ldg(pA + ((e1 & 1023u) << 10));
                    a2 = __ldg(pA + ((e2 & 1023u) << 10));
                    a3 = __ldg(pA + ((e3 & 1023u) << 10));
                }
                if (hasB) {
                    b0 = __ldg(pB + ((e0 & 1023u) << 10));
                    b1 = __ldg(pB + ((e1 & 1023u) << 10));
                    b2 = __ldg(pB + ((e2 & 1023u) << 10));
                    b3 = __ldg(pB + ((e3 & 1023u) << 10));
                }
            }
            F2U w;
            w.f = make_float2(x0, y0); ACC8P(f0, w.u);
            w.f = make_float2(x1, y1); ACC8P(f1, w.u);
            w.f = make_float2(x2, y2); ACC8P(f2, w.u);
            w.f = make_float2(x3, y3); ACC8P(f3, w.u);
        }
    }
    for (int i = nb << 2; i < cnt; i++) {
        unsigned e = list[i];
        float xa = hasA ? __ldg(pA + ((e & 1023u) << 10)) : 0.f;
        float xb = hasB ? __ldg(pB + ((e & 1023u) << 10)) : 0.f;
        F2U w;
        w.f = make_float2(xa, xb);
        ACC8P(e, w.u);
    }
}

// ---------------------------------------------------------------------------
__global__ void __launch_bounds__(NTHR) snn_kernel(
    const float* __restrict__ input,
    const float* __restrict__ W1, const float* __restrict__ b1,
    const float* __restrict__ b2, const float* __restrict__ b3,
    const float* __restrict__ W4, const float* __restrict__ b4,
    float* __restrict__ out) {
    __shared__ __align__(16) unsigned listA[HID];
    __shared__ __align__(16) unsigned listB[HID];
    __shared__ int s_warp[8];
    __shared__ float xsh[G * 8];
    __shared__ float4 s_red4[8];
    __shared__ __align__(16) ulonglong2 dcsh[G * NTHR];  // const L1 drive

    const int tid = threadIdx.x;
    const int n0 = blockIdx.x * G;
    const int h0 = 4 * tid;  // layer-1 units h0..h0+3

    // column-slot -> unit maps and biases
    int h2s[4], h3s[4];
    float b2v[4], b3v[4];
#pragma unroll
    for (int s = 0; s < 4; s++) {
        int c = tid + 256 * s;
        h2s[s] = __ldg(&g_u2[c]);
        h3s[s] = __ldg(&g_u3[c]);
        b2v[s] = __ldg(b2 + h2s[s]);
        b3v[s] = __ldg(b3 + h3s[s]);
    }

    float m1[4][G], m2[4][G], m3[4][G];
#pragma unroll
    for (int k = 0; k < 4; k++)
#pragma unroll
        for (int g = 0; g < G; g++) {
            m1[k][g] = 0.f; m2[k][g] = 0.f; m3[k][g] = 0.f;
        }
    unsigned ss1l[4] = {0,0,0,0}, ss1h[4] = {0,0,0,0};
    unsigned ss2l[4] = {0,0,0,0}, ss2h[4] = {0,0,0,0};
    unsigned ss3l[4] = {0,0,0,0}, ss3h[4] = {0,0,0,0};

    const float4* W14 = reinterpret_cast<const float4*>(W1);

    // constant layer-1 drive (t >= 12 uses input slice at 776)
    if (tid < G * 8)
        xsh[tid] = __ldg(input + (n0 + (tid >> 3)) * 784 + 776 + (tid & 7));
    __syncthreads();
    {
        float4 bq1 = __ldg(reinterpret_cast<const float4*>(b1) + tid);
        float w1r[4][8];
#pragma unroll
        for (int k = 0; k < 4; k++) {
            float4 a = __ldg(W14 + (h0 + k) * 2);
            float4 c = __ldg(W14 + (h0 + k) * 2 + 1);
            w1r[k][0] = a.x; w1r[k][1] = a.y; w1r[k][2] = a.z; w1r[k][3] = a.w;
            w1r[k][4] = c.x; w1r[k][5] = c.y; w1r[k][6] = c.z; w1r[k][7] = c.w;
        }
        float bb[4] = {bq1.x, bq1.y, bq1.z, bq1.w};
#pragma unroll
        for (int g = 0; g < G; g++) {
            const float* x = &xsh[g * 8];
            float s[4];
#pragma unroll
            for (int k = 0; k < 4; k++) {
                float acc = bb[k];
#pragma unroll
                for (int i = 0; i < 8; i++) acc += x[i] * w1r[k][i];
                s[k] = acc;
            }
            F2U lo, hi;
            lo.f = make_float2(s[0], s[1]);
            hi.f = make_float2(s[2], s[3]);
            dcsh[g * NTHR + tid] = make_ulonglong2(lo.u, hi.u);
        }
    }
    __syncthreads();

    int w0 = 66;    // (33*t + 66) % 98 at t=0
    int g3lo = 25;  // (25*tau + 25) % 49 at tau=0

    for (int t = 0; t < TSTEPS; t++) {
        const int par = t & 1;

        // ---------- layer 1 drive (packed pairs) ----------
        unsigned long long d1L[G], d1H[G];
        if (t < 12) {
            if (tid < G * 8)
                xsh[tid] =
                    __ldg(input + (n0 + (tid >> 3)) * 784 + t * 8 + (tid & 7));
            __syncthreads();
            float4 bq1 = __ldg(reinterpret_cast<const float4*>(b1) + tid);
            float w1r[4][8];
#pragma unroll
            for (int k = 0; k < 4; k++) {
                float4 a = __ldg(W14 + (h0 + k) * 2);
                float4 c = __ldg(W14 + (h0 + k) * 2 + 1);
                w1r[k][0] = a.x; w1r[k][1] = a.y; w1r[k][2] = a.z; w1r[k][3] = a.w;
                w1r[k][4] = c.x; w1r[k][5] = c.y; w1r[k][6] = c.z; w1r[k][7] = c.w;
            }
            float bb[4] = {bq1.x, bq1.y, bq1.z, bq1.w};
#pragma unroll
            for (int g = 0; g < G; g++) {
                const float* x = &xsh[g * 8];
                float s[4];
#pragma unroll
                for (int k = 0; k < 4; k++) {
                    float acc = bb[k];
#pragma unroll
                    for (int i = 0; i < 8; i++) acc += x[i] * w1r[k][i];
                    s[k] = acc;
                }
                F2U lo, hi;
                lo.f = make_float2(s[0], s[1]);
                hi.f = make_float2(s[2], s[3]);
                d1L[g] = lo.u;
                d1H[g] = hi.u;
            }
            __syncthreads();
        } else {
#pragma unroll
            for (int g = 0; g < G; g++) {
                ulonglong2 v = dcsh[g * NTHR + tid];
                d1L[g] = v.x;
                d1H[g] = v.y;
            }
        }

        // ---------- layer 1 update: eligible units k = par, par+2 ----------
        // (cycles >= 2 => never eligible on consecutive steps => prev spike
        //  at any eligible update is always 0: m = m*0.5 + d)
        unsigned mk0 = 0, mk2 = 0;
        if (par == 0) {
#pragma unroll
            for (int g = 0; g < G; g++) {
                F2U uL, uH; uL.u = d1L[g]; uH.u = d1H[g];
                float na = m1[0][g] * 0.5f + uL.f.x;
                float nc = m1[2][g] * 0.5f + uH.f.x;
                m1[0][g] = na; m1[2][g] = nc;
                if (na > 0.5f) mk0 |= 1u << g;
                if (nc > 0.5f) mk2 |= 1u << g;
            }
            ss1l[0] += spread4(mk0); ss1h[0] += spread4(mk0 >> 4);
            ss1l[2] += spread4(mk2); ss1h[2] += spread4(mk2 >> 4);
        } else {
#pragma unroll
            for (int g = 0; g < G; g++) {
                F2U uL, uH; uL.u = d1L[g]; uH.u = d1H[g];
                float na = m1[1][g] * 0.5f + uL.f.y;
                float nc = m1[3][g] * 0.5f + uH.f.y;
                m1[1][g] = na; m1[3][g] = nc;
                if (na > 0.5f) mk0 |= 1u << g;
                if (nc > 0.5f) mk2 |= 1u << g;
            }
            ss1l[1] += spread4(mk0); ss1h[1] += spread4(mk0 >> 4);
            ss1l[3] += spread4(mk2); ss1h[3] += spread4(mk2 >> 4);
        }

        int excl, cnt;
        block_scan((mk0 ? 1 : 0) + (mk2 ? 1 : 0), tid, s_warp, excl, cnt);
        {
            int p = excl;
            if (mk0) listA[p++] = (mk0 << 10) | (unsigned)(h0 + par);
            if (mk2) listA[p] = (mk2 << 10) | (unsigned)(h0 + par + 2);
        }
        __syncthreads();

        // ---------- layer 2: windowed gather + update ----------
        {
            int lo = __ldg(&g_S2[w0]);
            int hiI = w0 + 33;
            bool wrap = hiI > 98;
            int hi = wrap ? __ldg(&g_S2[hiI - 98]) : __ldg(&g_S2[hiI]);
            bool inw[4];
            int sF = -1, cA = 0, cB = 0;
            float bA = 0.f, bB = 0.f;
            bool hasB = false;
#pragma unroll
            for (int s = 0; s < 4; s++) {
                int c = tid + 256 * s;
                bool in = wrap ? (c >= lo || c < hi) : (c >= lo && c < hi);
                inw[s] = in;
                if (in) {
                    if (sF < 0) { sF = s; cA = c; bA = b2v[s]; }
                    else { cB = c; bB = b2v[s]; hasB = true; }
                }
            }
            if (!hasB) cB = cA;
            unsigned long long acc[G];
            {
                F2U bi; bi.f = make_float2(bA, bB);
#pragma unroll
                for (int g = 0; g < G; g++) acc[g] = bi.u;
            }
            gatherW(listA, cnt, g_W2J, cA, cB, true, hasB, acc);

            unsigned msk[4];
            int cl = 0;
#pragma unroll
            for (int s = 0; s < 4; s++) {
                msk[s] = 0;
                if (inw[s]) {
                    bool useY = (s != sF);
                    unsigned mm = 0;
#pragma unroll
                    for (int g = 0; g < G; g++) {
                        F2U u; u.u = acc[g];
                        float d = useY ? u.f.y : u.f.x;
                        float nm = m2[s][g] * 0.5f + d;
                        m2[s][g] = nm;
                        if (nm > 0.5f) mm |= 1u << g;
                    }
                    msk[s] = mm;
                    ss2l[s] += spread4(mm);
                    ss2h[s] += spread4(mm >> 4);
                    cl += (mm ? 1 : 0);
                }
            }
            block_scan(cl, tid, s_warp, excl, cnt);
            {
                int p = excl;
#pragma unroll
                for (int s = 0; s < 4; s++)
                    if (msk[s]) listB[p++] = (msk[s] << 10) | (unsigned)h2s[s];
            }
            __syncthreads();
        }

        // ---------- layer 3: windowed gather + update ----------
        {
            int lo = __ldg(&g_S3[par][g3lo]);
            int hiI = g3lo + 25;
            bool wrap = hiI > 49;
            int hi = wrap ? __ldg(&g_S3[par][hiI - 49]) : __ldg(&g_S3[par][hiI]);
            bool inw[4];
            int sF = -1, cA = 0, cB = 0;
            float bA = 0.f, bB = 0.f;
            bool hasB = false;
#pragma unroll
            for (int s = 0; s < 4; s++) {
                int c = tid + 256 * s;
                bool blk = ((s >> 1) == par);
                bool in = blk && (wrap ? (c >= lo || c < hi)
                                       : (c >= lo && c < hi));
                inw[s] = in;
                if (in) {
                    if (sF < 0) { sF = s; cA = c; bA = b3v[s]; }
                    else { cB = c; bB = b3v[s]; hasB = true; }
                }
            }
            bool hasA = sF >= 0;
            if (!hasA) cA = tid;
            if (!hasB) cB = cA;
            unsigned long long acc[G];
            {
                F2U bi; bi.f = make_float2(bA, bB);
#pragma unroll
                for (int g = 0; g < G; g++) acc[g] = bi.u;
            }
            gatherW(listB, cnt, g_W3J, cA, cB, hasA, hasB, acc);

#pragma unroll
            for (int s = 0; s < 4; s++) {
                if (inw[s]) {
                    bool useY = (s != sF);
                    unsigned mm = 0;
#pragma unroll
                    for (int g = 0; g < G; g++) {
                        F2U u; u.u = acc[g];
                        float d = useY ? u.f.y : u.f.x;
                        float nm = m3[s][g] * 0.5f + d;
                        m3[s][g] = nm;
                        if (nm > 0.5f) mm |= 1u << g;
                    }
                    ss3l[s] += spread4(mm);
                    ss3h[s] += spread4(mm >> 4);
                }
            }
        }

        // advance windows
        w0 += 33; if (w0 >= 98) w0 -= 98;
        if (par == 1) { g3lo += 25; if (g3lo >= 49) g3lo -= 49; }
    }

    // ------------------------- epilogue -------------------------
    const float inv = 1.0f / 98.0f;

    // layer-1 hidden (contiguous units h0..h0+3)
#pragma unroll
    for (int g = 0; g < G; g++) {
        int sh = 8 * (g & 3);
        const unsigned* l1 = (g < 4) ? ss1l : ss1h;
        float4 v1 = make_float4((float)((l1[0] >> sh) & 255u) * inv,
                                (float)((l1[1] >> sh) & 255u) * inv,
                                (float)((l1[2] >> sh) & 255u) * inv,
                                (float)((l1[3] >> sh) & 255u) * inv);
        *reinterpret_cast<float4*>(out + 10240 + (n0 + g) * HID + h0) = v1;
    }
    // layers 2,3 hidden (scattered by column->unit map)
#pragma unroll
    for (int s = 0; s < 4; s++) {
#pragma unroll
        for (int g = 0; g < G; g++) {
            int sh = 8 * (g & 3);
            float a2 = (float)(((g < 4 ? ss2l[s] : ss2h[s]) >> sh) & 255u);
            float a3 = (float)(((g < 4 ? ss3l[s] : ss3h[s]) >> sh) & 255u);
            out[10240 + 1048576 + (n0 + g) * HID + h2s[s]] = a2 * inv;
            out[10240 + 2097152 + (n0 + g) * HID + h3s[s]] = a3 * inv;
        }
    }

    // spike counts as floats for output GEMM
    float s3f[4][G];
#pragma unroll
    for (int s = 0; s < 4; s++)
#pragma unroll
        for (int g = 0; g < G; g++)
            s3f[s][g] =
                (float)(((g < 4 ? ss3l[s] : ss3h[s]) >> (8 * (g & 3))) & 255u);

    const int lane = tid & 31, wid = tid >> 5;

    // outputs[n] = (ss3 @ W4^T)/98 + b4
    for (int o = 0; o < 10; o++) {
        float w4s[4];
#pragma unroll
        for (int s = 0; s < 4; s++) w4s[s] = __ldg(W4 + o * HID + h3s[s]);
#pragma unroll
        for (int half = 0; half < 2; half++) {
            float4 v;
            v.x = s3f[0][half * 4 + 0] * w4s[0] + s3f[1][half * 4 + 0] * w4s[1] +
                  s3f[2][half * 4 + 0] * w4s[2] + s3f[3][half * 4 + 0] * w4s[3];
            v.y = s3f[0][half * 4 + 1] * w4s[0] + s3f[1][half * 4 + 1] * w4s[1] +
                  s3f[2][half * 4 + 1] * w4s[2] + s3f[3][half * 4 + 1] * w4s[3];
            v.z = s3f[0][half * 4 + 2] * w4s[0] + s3f[1][half * 4 + 2] * w4s[1] +
                  s3f[2][half * 4 + 2] * w4s[2] + s3f[3][half * 4 + 2] * w4s[3];
            v.w = s3f[0][half * 4 + 3] * w4s[0] + s3f[1][half * 4 + 3] * w4s[1] +
                  s3f[2][half * 4 + 3] * w4s[2] + s3f[3][half * 4 + 3] * w4s[3];
#pragma unroll
            for (int off = 16; off > 0; off >>= 1) {
                v.x += __shfl_down_sync(0xffffffffu, v.x, off);
                v.y += __shfl_down_sync(0xffffffffu, v.y, off);
                v.z += __shfl_down_sync(0xffffffffu, v.z, off);
                v.w += __shfl_down_sync(0xffffffffu, v.w, off);
            }
            if (lane == 0) s_red4[wid] = v;
            __syncthreads();
            if (tid == 0) {
                float4 s = make_float4(0, 0, 0, 0);
#pragma unroll
                for (int w = 0; w < 8; w++) {
                    s.x += s_red4[w].x; s.y += s_red4[w].y;
                    s.z += s_red4[w].z; s.w += s_red4[w].w;
                }
                float bo = __ldg(b4 + o);
                out[(n0 + half * 4 + 0) * 10 + o] = s.x / 98.0f + bo;
                out[(n0 + half * 4 + 1) * 10 + o] = s.y / 98.0f + bo;
                out[(n0 + half * 4 + 2) * 10 + o] = s.z / 98.0f + bo;
                out[(n0 + half * 4 + 3) * 10 + o] = s.w / 98.0f + bo;
            }
            __syncthreads();
        }
    }

    // layer firing-rate partial sums (exact integers in fp32)
    unsigned c1 = 0, c2 = 0, c3 = 0;
#pragma unroll
    for (int s = 0; s < 4; s++) {
        c1 = bytesum(ss1l[s], c1); c1 = bytesum(ss1h[s], c1);
        c2 = bytesum(ss2l[s], c2); c2 = bytesum(ss2h[s], c2);
        c3 = bytesum(ss3l[s], c3); c3 = bytesum(ss3h[s], c3);
    }
    {
        float4 v = make_float4((float)c1, (float)c2, (float)c3, 0.0f);
#pragma unroll
        for (int off = 16; off > 0; off >>= 1) {
            v.x += __shfl_down_sync(0xffffffffu, v.x, off);
            v.y += __shfl_down_sync(0xffffffffu, v.y, off);
            v.z += __shfl_down_sync(0xffffffffu, v.z, off);
        }
        if (lane == 0) s_red4[wid] = v;
        __syncthreads();
        if (tid == 0) {
            float s0 = 0, s1 = 0, s2 = 0;
#pragma unroll
            for (int w = 0; w < 8; w++) {
                s0 += s_red4[w].x; s1 += s_red4[w].y; s2 += s_red4[w].z;
            }
            atomicAdd(&g_fr[0], s0);
            atomicAdd(&g_fr[1], s1);
            atomicAdd(&g_fr[2], s2);
        }
    }
}

__global__ void finalize_kernel(float* __restrict__ out) {
    if (threadIdx.x < 3)
        out[3155968 + threadIdx.x] = g_fr[threadIdx.x] / 102760448.0f;
}

extern "C" void kernel_launch(void* const* d_in, const int* in_sizes, int n_in,
                              void* d_out, int out_size) {
    const float* input = (const float*)d_in[0];
    const float* W1 = (const float*)d_in[1];
    const float* b1 = (const float*)d_in[2];
    const float* W2 = (const float*)d_in[3];
    const float* b2 = (const float*)d_in[4];
    const float* W3 = (const float*)d_in[5];
    const float* b3 = (const float*)d_in[6];
    const float* W4 = (const float*)d_in[7];
    const float* b4 = (const float*)d_in[8];
    (void)in_sizes; (void)n_in; (void)out_size;

    init_tables<<<1, 1>>>();
    dim3 pgrid(HID / 32, HID / 32, 2);
    prep_kernel<<<pgrid, dim3(32, 32)>>>(W2, W3);
    snn_kernel<<<NCTA, NTHR>>>(input, W1, b1, b2, b3, W4, b4, (float*)d_out);
    finalize_kernel<<<1, 32>>>((float*)d_out);
}